// round 3
// baseline (speedup 1.0000x reference)
#include <cuda_runtime.h>

#define Z 32  // batch chunks of 8

// Partial batch sums of x: [z][i][c] = [32][8][1152]  (1.18 MB)
__device__ float g_part[Z * 8 * 1152];

// Kernel A: g_part[z][i][c] = sum over the 8 batches of chunk z of x[b,i,c].
// x: [256, 8, 1152] f32 viewed as [256, 2304] float4 rows.
__global__ void __launch_bounds__(256) reduce_x_kernel(const float* __restrict__ x) {
    const int col = blockIdx.x * 256 + threadIdx.x;  // 0..2303 float4 columns
    const int z = blockIdx.y;                        // 0..31
    const float4* p = reinterpret_cast<const float4*>(x) + (size_t)z * 8 * 2304 + col;
    float4 a = make_float4(0.f, 0.f, 0.f, 0.f);
    #pragma unroll
    for (int b = 0; b < 8; ++b) {
        const float4 v = p[(size_t)b * 2304];
        a.x += v.x; a.y += v.y; a.z += v.z; a.w += v.w;
    }
    reinterpret_cast<float4*>(g_part)[(size_t)z * 2304 + col] = a;
}

// Kernel B: one 160-thread block per capsule. Thread t -> (u = t>>4, s = t&15).
// us-matvec + all 3 routing iterations fused. s-reductions via half-warp
// shuffles; softmax exps computed once per block (threads t<10).
__global__ void __launch_bounds__(160) routing_kernel(const float* __restrict__ W,
                                                      float* __restrict__ out) {
    const int c = blockIdx.x;       // 1152
    const int t = threadIdx.x;      // 0..159
    const int u = t >> 4;

    __shared__ float xs[8];
    __shared__ float sb[10];   // routing logits
    __shared__ float se[10];   // exp(b - m)

    // Start the big W stream first (2 x LDG.128 per thread, coalesced).
    const float4* wp = reinterpret_cast<const float4*>(W + (size_t)c * 1280) + 2 * t;
    const float4 w0 = __ldg(wp);
    const float4 w1 = __ldg(wp + 1);

    // xs[i] = sum of Z partials (threads 0..7; 32 independent L2-cached loads).
    if (t < 8) {
        float a = 0.f;
        #pragma unroll
        for (int z = 0; z < Z; ++z)
            a += g_part[(z * 8 + t) * 1152 + c];
        xs[t] = a;
    }
    if (t < 10) sb[t] = 0.f;
    __syncthreads();

    // u_sum (batch-summed u_hat) for this (u,s)
    const float us = w0.x * xs[0] + w0.y * xs[1] + w0.z * xs[2] + w0.w * xs[3]
                   + w1.x * xs[4] + w1.y * xs[5] + w1.z * xs[6] + w1.w * xs[7];

    float v = 0.f;
    float cij = 0.1f;   // iteration 1: softmax of all-zero logits = 1/10 exactly

    #pragma unroll
    for (int it = 0; it < 3; ++it) {
        const float sj = cij * us;

        // ||s_j||^2 over 16 s-lanes (xor offsets < 16 stay inside half-warp)
        float msq = sj * sj;
        #pragma unroll
        for (int off = 8; off; off >>= 1)
            msq += __shfl_xor_sync(0xffffffffu, msq, off);

        v = msq / (1.0f + msq) * sj * rsqrtf(msq);

        if (it < 2) {
            // agreement: (sum_s u_sum * v) / B
            float a = us * v;
            #pragma unroll
            for (int off = 8; off; off >>= 1)
                a += __shfl_xor_sync(0xffffffffu, a, off);
            if ((t & 15) == 0) sb[u] += a * (1.0f / 256.0f);  // one writer per u
            __syncthreads();

            // softmax numerators, computed once per block
            if (t < 10) {
                float m = sb[0];
                #pragma unroll
                for (int k = 1; k < 10; ++k) m = fmaxf(m, sb[k]);
                se[t] = __expf(sb[t] - m);
            }
            __syncthreads();

            float denom = se[0];
            #pragma unroll
            for (int k = 1; k < 10; ++k) denom += se[k];
            cij = se[u] / denom;
        }
    }

    out[(size_t)c * 160 + t] = v;   // coalesced: t = u*16 + s
}

extern "C" void kernel_launch(void* const* d_in, const int* in_sizes, int n_in,
                              void* d_out, int out_size) {
    const float* x = (const float*)d_in[0];   // [256, 8, 1152]
    const float* W = (const float*)d_in[1];   // [1, 1152, 10, 16, 8]
    float* out = (float*)d_out;               // [1152, 10, 16]

    reduce_x_kernel<<<dim3(9, Z), 256>>>(x);
    routing_kernel<<<1152, 160>>>(W, out);
}